// round 7
// baseline (speedup 1.0000x reference)
#include <cuda_runtime.h>
#include <cuda_bf16.h>
#include <cstdint>

#define NN 16384
#define EE 262144
#define H1C 256
#define DD 512
#define NEG_SLOPE 0.2f

// ---------------- device scratch ----------------
// Packed split-bf16 activation "A-layout": one uint32 per fp32 element;
// word[2i] = bf16x2(hi(e2i),hi(e2i+1)), word[2i+1] = bf16x2(lo pair).
__device__ uint32_t g_xp [NN * H1C];
__device__ uint32_t g_h0p[NN * H1C];
__device__ uint32_t g_h1p[(size_t)NN * DD];
__device__ float    g_g1[(size_t)NN * DD];
__device__ float    g_g2[(size_t)NN * DD];
// Packed weights "B-layout": uint4 per (4k x 1n): {hi(k0,k1),lo(k0,k1),hi(k2,k3),lo(k2,k3)}
__device__ uint4 g_wfcp[(H1C / 4) * H1C];
__device__ uint4 g_w1p [(H1C / 4) * DD];
__device__ uint4 g_w2p [(DD / 4) * DD];

__device__ float g_al1[NN * 4];
__device__ float g_al2[NN * 2];
__device__ int   g_deg[NN];
__device__ int   g_cursor[NN];
__device__ int   g_off[NN + 1];
__device__ int   g_esrc[EE];
__device__ float g_alpha1[(size_t)EE * 2];
__device__ float g_salpha1[NN * 2];
__device__ float g_alpha2[EE];
__device__ float g_salpha2[NN];

// ---------------- split helpers ----------------
__device__ __forceinline__ void split_pack(float x0, float x1,
                                           uint32_t& hi, uint32_t& lo) {
    __nv_bfloat16 h0 = __float2bfloat16_rn(x0);
    __nv_bfloat16 h1 = __float2bfloat16_rn(x1);
    hi = (uint32_t)__bfloat16_as_ushort(h0) |
         ((uint32_t)__bfloat16_as_ushort(h1) << 16);
    float l0 = x0 - __bfloat162float(h0);
    float l1 = x1 - __bfloat162float(h1);
    __nv_bfloat162 lp = __floats2bfloat162_rn(l0, l1);
    lo = *reinterpret_cast<const uint32_t*>(&lp);
}

// ---------------- pack kernels ----------------
__global__ void pack_a_kernel(const float* __restrict__ X,
                              uint32_t* __restrict__ P, int npairs) {
    int i = blockIdx.x * blockDim.x + threadIdx.x;
    if (i < npairs) {
        float2 v = *(const float2*)(X + 2 * (size_t)i);
        split_pack(v.x, v.y, P[2 * (size_t)i], P[2 * (size_t)i + 1]);
    }
}

__global__ void pack_b_kernel(const float* __restrict__ W,
                              uint4* __restrict__ P, int K, int N) {
    int idx = blockIdx.x * blockDim.x + threadIdx.x;
    int total = (K / 4) * N;
    if (idx >= total) return;
    int c = idx / N;
    int n = idx - c * N;
    const float* wp = W + (size_t)(4 * c) * N + n;
    float w0 = wp[0], w1 = wp[N], w2 = wp[2 * N], w3 = wp[3 * N];
    uint4 o;
    split_pack(w0, w1, o.x, o.y);
    split_pack(w2, w3, o.z, o.w);
    P[idx] = o;
}

// ---------------- CSR construction ----------------
__global__ void zero_kernel() {
    int i = blockIdx.x * blockDim.x + threadIdx.x;
    if (i < NN) { g_deg[i] = 0; g_cursor[i] = 0; }
}
__global__ void count_kernel(const int* __restrict__ adj) {
    int i = blockIdx.x * blockDim.x + threadIdx.x;
    if (i < EE) atomicAdd(&g_deg[adj[EE + i]], 1);
}
__global__ void scan_kernel() {
    int t = threadIdx.x;
    int base_i = t * 64;
    int sum = 0;
    #pragma unroll 4
    for (int k = 0; k < 64; k++) sum += g_deg[base_i + k];
    __shared__ int part[256];
    part[t] = sum;
    __syncthreads();
    for (int s = 1; s < 256; s <<= 1) {
        int v = (t >= s) ? part[t - s] : 0;
        __syncthreads();
        part[t] += v;
        __syncthreads();
    }
    int run = (t > 0) ? part[t - 1] : 0;
    for (int k = 0; k < 64; k++) {
        g_off[base_i + k] = run;
        run += g_deg[base_i + k];
    }
    if (t == 255) g_off[NN] = run;
}
__global__ void scatter_kernel(const int* __restrict__ adj) {
    int i = blockIdx.x * blockDim.x + threadIdx.x;
    if (i < EE) {
        int src = adj[i];
        int dst = adj[EE + i];
        int p = g_off[dst] + atomicAdd(&g_cursor[dst], 1);
        g_esrc[p] = src;
    }
}

// ================= Tensor-core GEMM, cp.async 4-stage pipeline =================
// Conflict-free SMEM layout: word = line*32 + 4*(lc^M) + 2*(kw&1)+h (verified R4/R5)
__device__ __forceinline__ int smw(int outer, int kw) {
    int line = outer >> 1;
    int M = ((line & 3) << 1) | ((line >> 2) & 1);
    int lc = ((outer & 1) << 2) + (kw >> 1);
    return line * 32 + (((lc ^ M) << 2) | ((kw & 1) << 1));
}

__device__ __forceinline__ void mma16816(float* d, const uint32_t* a,
                                         const uint32_t* b) {
    asm volatile(
        "mma.sync.aligned.m16n8k16.row.col.f32.bf16.bf16.f32 "
        "{%0,%1,%2,%3}, {%4,%5,%6,%7}, {%8,%9}, {%0,%1,%2,%3};\n"
        : "+f"(d[0]), "+f"(d[1]), "+f"(d[2]), "+f"(d[3])
        : "r"(a[0]), "r"(a[1]), "r"(a[2]), "r"(a[3]),
          "r"(b[0]), "r"(b[1]));
}

__device__ __forceinline__ uint32_t smem_u32(const void* p) {
    uint32_t a;
    asm("{ .reg .u64 t; cvta.to.shared.u64 t, %1; cvt.u32.u64 %0, t; }"
        : "=r"(a) : "l"(p));
    return a;
}
__device__ __forceinline__ void cp16(uint32_t dst, const void* src) {
    asm volatile("cp.async.cg.shared.global [%0], [%1], 16;"
                 :: "r"(dst), "l"(src));
}
#define CP_COMMIT() asm volatile("cp.async.commit_group;" ::: "memory")

// Stage = 16 KB: A words [0,2048), B words [2048,4096)
#define STG_BYTES 16384
#define NSTG 4

__device__ __forceinline__ void fill_stage(
    const uint32_t* __restrict__ Ap, const uint4* __restrict__ Bp,
    int brow, int bcol, int K, int N, int k0, int tid, uint32_t sbase)
{
    int c4 = tid & 3;
    #pragma unroll
    for (int f = 0; f < 2; f++) {
        int row = (tid >> 2) + 64 * f;
        cp16(sbase + 4 * smw(row, 2 * c4),
             Ap + (size_t)(brow + row) * K + k0 + 4 * c4);
    }
    int tc = tid >> 6;
    int m  = tid & 63;
    const uint4* bp = Bp + (size_t)((k0 >> 2) + tc) * N + bcol + 2 * m;
    uint32_t bB = sbase + 8192;
    cp16(bB + 4 * smw(2 * m,     2 * tc), bp);
    cp16(bB + 4 * smw(2 * m + 1, 2 * tc), bp + 1);
}

// OUT_MODE: 0 = fp32 plain, 1 = packed split-bf16 with bias+relu
template <int OUT_MODE>
__global__ __launch_bounds__(256, 2) void tgemm_p_kernel(
    const uint32_t* __restrict__ Ap, const uint4* __restrict__ Bp,
    const float* __restrict__ bias, void* __restrict__ Cout,
    int M, int N, int K)
{
    extern __shared__ uint32_t dynsm[];
    const uint32_t sb = smem_u32(dynsm);

    const int tid  = threadIdx.x;
    const int lane = tid & 31;
    const int wid  = tid >> 5;
    const int wm   = wid & 1;
    const int wn   = wid >> 1;
    const int brow = blockIdx.y * 128;
    const int bcol = blockIdx.x * 128;

    float acc[4][4][4];
    #pragma unroll
    for (int i = 0; i < 4; i++)
        #pragma unroll
        for (int j = 0; j < 4; j++)
            #pragma unroll
            for (int q = 0; q < 4; q++) acc[i][j][q] = 0.f;

    const int iters = K >> 4;

    #pragma unroll
    for (int s = 0; s < NSTG - 1; s++) {
        if (s < iters) {
            fill_stage(Ap, Bp, brow, bcol, K, N, s << 4, tid, sb + s * STG_BYTES);
            CP_COMMIT();
        }
    }

    const int c  = lane & 3;
    const int r4 = lane >> 2;
    const int offA0 = smw(r4, c);
    const int offA1 = smw(8 + r4, c);
    const int offA2 = smw(r4, c + 4);
    const int offA3 = smw(8 + r4, c + 4);

    for (int it = 0; it < iters; ++it) {
        int rem = iters - 1 - it;
        if (rem >= 2)      asm volatile("cp.async.wait_group 2;" ::: "memory");
        else if (rem == 1) asm volatile("cp.async.wait_group 1;" ::: "memory");
        else               asm volatile("cp.async.wait_group 0;" ::: "memory");
        __syncthreads();

        uint32_t* buf  = dynsm + (it & (NSTG - 1)) * 4096;
        uint32_t* Abuf = buf;
        uint32_t* Bbuf = buf + 2048;

        uint2 bfr[4][2];
        #pragma unroll
        for (int ni = 0; ni < 4; ni++) {
            int base = wn * 512;
            bfr[ni][0] = *(const uint2*)&Bbuf[base + smw(ni * 8 + r4, c)];
            bfr[ni][1] = *(const uint2*)&Bbuf[base + smw(ni * 8 + r4, c + 4)];
        }
        #pragma unroll
        for (int mi = 0; mi < 4; mi++) {
            int base = (wm * 64 + mi * 16) * 16;
            uint2 a0 = *(const uint2*)&Abuf[base + offA0];
            uint2 a1 = *(const uint2*)&Abuf[base + offA1];
            uint2 a2 = *(const uint2*)&Abuf[base + offA2];
            uint2 a3 = *(const uint2*)&Abuf[base + offA3];
            uint32_t ah[4] = {a0.x, a1.x, a2.x, a3.x};
            uint32_t al[4] = {a0.y, a1.y, a2.y, a3.y};
            #pragma unroll
            for (int ni = 0; ni < 4; ni++) {
                uint32_t bh[2] = {bfr[ni][0].x, bfr[ni][1].x};
                uint32_t bl[2] = {bfr[ni][0].y, bfr[ni][1].y};
                mma16816(acc[mi][ni], ah, bh);
                mma16816(acc[mi][ni], ah, bl);
                mma16816(acc[mi][ni], al, bh);
            }
        }

        if (it + NSTG - 1 < iters) {
            fill_stage(Ap, Bp, brow, bcol, K, N, (it + NSTG - 1) << 4, tid,
                       sb + ((it + NSTG - 1) & (NSTG - 1)) * STG_BYTES);
            CP_COMMIT();
        }
    }

    #pragma unroll
    for (int mi = 0; mi < 4; mi++) {
        int row = brow + wm * 64 + mi * 16 + r4;
        #pragma unroll
        for (int ni = 0; ni < 4; ni++) {
            int col = bcol + wn * 32 + ni * 8 + 2 * c;
            float2 v0 = make_float2(acc[mi][ni][0], acc[mi][ni][1]);
            float2 v1 = make_float2(acc[mi][ni][2], acc[mi][ni][3]);
            if (OUT_MODE == 1) {
                float2 bb = *(const float2*)(bias + col);
                v0.x = fmaxf(v0.x + bb.x, 0.f); v0.y = fmaxf(v0.y + bb.y, 0.f);
                v1.x = fmaxf(v1.x + bb.x, 0.f); v1.y = fmaxf(v1.y + bb.y, 0.f);
                uint2 w0, w1;
                split_pack(v0.x, v0.y, w0.x, w0.y);
                split_pack(v1.x, v1.y, w1.x, w1.y);
                uint32_t* P = (uint32_t*)Cout;
                *(uint2*)(P + (size_t)row * N + col)       = w0;
                *(uint2*)(P + (size_t)(row + 8) * N + col) = w1;
            } else {
                float* C = (float*)Cout;
                *(float2*)(C + (size_t)row * N + col)       = v0;
                *(float2*)(C + (size_t)(row + 8) * N + col) = v1;
            }
        }
    }
}

// ---------------- attention scalars ----------------
__global__ void al1_kernel(const float* __restrict__ a_src,
                           const float* __restrict__ a_dst)
{
    int gw = (blockIdx.x * blockDim.x + threadIdx.x) >> 5;
    if (gw >= NN) return;
    int lane = threadIdx.x & 31;
    const float4* row = (const float4*)(g_g1 + (size_t)gw * DD);
    const float4* as4 = (const float4*)a_src;
    const float4* ad4 = (const float4*)a_dst;
    float s0 = 0.f, s1 = 0.f, d0 = 0.f, d1 = 0.f;
    for (int c = lane; c < 128; c += 32) {
        float4 v = row[c];
        float4 a = as4[c];
        float4 b = ad4[c];
        float sv = v.x * a.x + v.y * a.y + v.z * a.z + v.w * a.w;
        float dv = v.x * b.x + v.y * b.y + v.z * b.z + v.w * b.w;
        if (c < 64) { s0 += sv; d0 += dv; } else { s1 += sv; d1 += dv; }
    }
    #pragma unroll
    for (int o = 16; o; o >>= 1) {
        s0 += __shfl_down_sync(0xffffffffu, s0, o);
        s1 += __shfl_down_sync(0xffffffffu, s1, o);
        d0 += __shfl_down_sync(0xffffffffu, d0, o);
        d1 += __shfl_down_sync(0xffffffffu, d1, o);
    }
    if (lane == 0) {
        g_al1[gw * 4 + 0] = s0;
        g_al1[gw * 4 + 1] = s1;
        g_al1[gw * 4 + 2] = d0;
        g_al1[gw * 4 + 3] = d1;
    }
}

__global__ void al2_kernel(const float* __restrict__ a_src,
                           const float* __restrict__ a_dst)
{
    int gw = (blockIdx.x * blockDim.x + threadIdx.x) >> 5;
    if (gw >= NN) return;
    int lane = threadIdx.x & 31;
    const float4* row = (const float4*)(g_g2 + (size_t)gw * DD);
    const float4* as4 = (const float4*)a_src;
    const float4* ad4 = (const float4*)a_dst;
    float s = 0.f, d = 0.f;
    for (int c = lane; c < 128; c += 32) {
        float4 v = row[c];
        float4 a = as4[c];
        float4 b = ad4[c];
        s += v.x * a.x + v.y * a.y + v.z * a.z + v.w * a.w;
        d += v.x * b.x + v.y * b.y + v.z * b.z + v.w * b.w;
    }
    #pragma unroll
    for (int o = 16; o; o >>= 1) {
        s += __shfl_down_sync(0xffffffffu, s, o);
        d += __shfl_down_sync(0xffffffffu, d, o);
    }
    if (lane == 0) {
        g_al2[gw * 2 + 0] = s;
        g_al2[gw * 2 + 1] = d;
    }
}

__device__ __forceinline__ float lrelu(float x) {
    return x > 0.f ? x : NEG_SLOPE * x;
}

// ---------------- edge softmax ----------------
__global__ void alpha1_kernel() {
    int n = (blockIdx.x * blockDim.x + threadIdx.x) >> 5;
    if (n >= NN) return;
    int lane = threadIdx.x & 31;
    int o = g_off[n];
    int cnt = g_off[n + 1] - o;
    float dd0 = g_al1[n * 4 + 2];
    float dd1 = g_al1[n * 4 + 3];

    float m0 = -1e30f, m1 = -1e30f;
    for (int i = lane; i <= cnt; i += 32) {
        int s = (i < cnt) ? g_esrc[o + i] : n;
        float e0 = lrelu(g_al1[s * 4 + 0] + dd0);
        float e1 = lrelu(g_al1[s * 4 + 1] + dd1);
        m0 = fmaxf(m0, e0);
        m1 = fmaxf(m1, e1);
    }
    #pragma unroll
    for (int x = 16; x; x >>= 1) {
        m0 = fmaxf(m0, __shfl_xor_sync(0xffffffffu, m0, x));
        m1 = fmaxf(m1, __shfl_xor_sync(0xffffffffu, m1, x));
    }
    float sum0 = 0.f, sum1 = 0.f;
    for (int i = lane; i <= cnt; i += 32) {
        int s = (i < cnt) ? g_esrc[o + i] : n;
        sum0 += expf(lrelu(g_al1[s * 4 + 0] + dd0) - m0);
        sum1 += expf(lrelu(g_al1[s * 4 + 1] + dd1) - m1);
    }
    #pragma unroll
    for (int x = 16; x; x >>= 1) {
        sum0 += __shfl_xor_sync(0xffffffffu, sum0, x);
        sum1 += __shfl_xor_sync(0xffffffffu, sum1, x);
    }
    float inv0 = 1.f / (sum0 + 1e-16f);
    float inv1 = 1.f / (sum1 + 1e-16f);
    for (int i = lane; i <= cnt; i += 32) {
        int s = (i < cnt) ? g_esrc[o + i] : n;
        float a0 = expf(lrelu(g_al1[s * 4 + 0] + dd0) - m0) * inv0;
        float a1 = expf(lrelu(g_al1[s * 4 + 1] + dd1) - m1) * inv1;
        if (i < cnt) {
            g_alpha1[(size_t)(o + i) * 2 + 0] = a0;
            g_alpha1[(size_t)(o + i) * 2 + 1] = a1;
        } else {
            g_salpha1[n * 2 + 0] = a0;
            g_salpha1[n * 2 + 1] = a1;
        }
    }
}

__global__ void alpha2_kernel() {
    int n = (blockIdx.x * blockDim.x + threadIdx.x) >> 5;
    if (n >= NN) return;
    int lane = threadIdx.x & 31;
    int o = g_off[n];
    int cnt = g_off[n + 1] - o;
    float dd = g_al2[n * 2 + 1];

    float m = -1e30f;
    for (int i = lane; i <= cnt; i += 32) {
        int s = (i < cnt) ? g_esrc[o + i] : n;
        m = fmaxf(m, lrelu(g_al2[s * 2] + dd));
    }
    #pragma unroll
    for (int x = 16; x; x >>= 1)
        m = fmaxf(m, __shfl_xor_sync(0xffffffffu, m, x));
    float sum = 0.f;
    for (int i = lane; i <= cnt; i += 32) {
        int s = (i < cnt) ? g_esrc[o + i] : n;
        sum += expf(lrelu(g_al2[s * 2] + dd) - m);
    }
    #pragma unroll
    for (int x = 16; x; x >>= 1)
        sum += __shfl_xor_sync(0xffffffffu, sum, x);
    float inv = 1.f / (sum + 1e-16f);
    for (int i = lane; i <= cnt; i += 32) {
        int s = (i < cnt) ? g_esrc[o + i] : n;
        float a = expf(lrelu(g_al2[s * 2] + dd) - m) * inv;
        if (i < cnt) g_alpha2[o + i] = a;
        else g_salpha2[n] = a;
    }
}

// ---------------- aggregation ----------------
__global__ __launch_bounds__(128) void agg1_kernel(const float* __restrict__ b1) {
    int n = blockIdx.x;
    int tid = threadIdx.x;
    int o = g_off[n];
    int cnt = g_off[n + 1] - o;
    int head = tid >> 6;

    __shared__ int   ssrc[128];
    __shared__ float sal[128 * 2];

    float4 acc = make_float4(0.f, 0.f, 0.f, 0.f);
    for (int base = 0; base < cnt; base += 128) {
        int m = min(128, cnt - base);
        if (tid < m) {
            ssrc[tid] = g_esrc[o + base + tid];
            sal[tid * 2 + 0] = g_alpha1[(size_t)(o + base + tid) * 2 + 0];
            sal[tid * 2 + 1] = g_alpha1[(size_t)(o + base + tid) * 2 + 1];
        }
        __syncthreads();
        for (int j = 0; j < m; j++) {
            float a = sal[j * 2 + head];
            const float4* r = (const float4*)(g_g1 + (size_t)ssrc[j] * DD);
            float4 v = r[tid];
            acc.x = fmaf(a, v.x, acc.x);
            acc.y = fmaf(a, v.y, acc.y);
            acc.z = fmaf(a, v.z, acc.z);
            acc.w = fmaf(a, v.w, acc.w);
        }
        __syncthreads();
    }
    {
        float a = g_salpha1[n * 2 + head];
        float4 v = ((const float4*)(g_g1 + (size_t)n * DD))[tid];
        acc.x = fmaf(a, v.x, acc.x);
        acc.y = fmaf(a, v.y, acc.y);
        acc.z = fmaf(a, v.z, acc.z);
        acc.w = fmaf(a, v.w, acc.w);
    }
    float4 bb = ((const float4*)b1)[tid];
    acc.x = fmaxf(acc.x + bb.x, 0.f);
    acc.y = fmaxf(acc.y + bb.y, 0.f);
    acc.z = fmaxf(acc.z + bb.z, 0.f);
    acc.w = fmaxf(acc.w + bb.w, 0.f);
    uint4 w;
    split_pack(acc.x, acc.y, w.x, w.y);
    split_pack(acc.z, acc.w, w.z, w.w);
    *(uint4*)(g_h1p + (size_t)n * DD + 4 * tid) = w;
}

__global__ __launch_bounds__(128) void agg2_kernel(const float* __restrict__ b2,
                                                   float* __restrict__ out) {
    int n = blockIdx.x;
    int tid = threadIdx.x;
    int o = g_off[n];
    int cnt = g_off[n + 1] - o;

    __shared__ int   ssrc[128];
    __shared__ float sal[128];

    float4 acc = make_float4(0.f, 0.f, 0.f, 0.f);
    for (int base = 0; base < cnt; base += 128) {
        int m = min(128, cnt - base);
        if (tid < m) {
            ssrc[tid] = g_esrc[o + base + tid];
            sal[tid] = g_alpha2[o + base + tid];
        }
        __syncthreads();
        for (int j = 0; j < m; j++) {
            float a = sal[j];
            const float4* r = (const float4*)(g_g2 + (size_t)ssrc[j] * DD);
            float4 v = r[tid];
            acc.x = fmaf(a, v.x, acc.x);
            acc.y = fmaf(a, v.y, acc.y);
            acc.z = fmaf(a, v.z, acc.z);
            acc.w = fmaf(a, v.w, acc.w);
        }
        __syncthreads();
    }
    {
        float a = g_salpha2[n];
        float4 v = ((const float4*)(g_g2 + (size_t)n * DD))[tid];
        acc.x = fmaf(a, v.x, acc.x);
        acc.y = fmaf(a, v.y, acc.y);
        acc.z = fmaf(a, v.z, acc.z);
        acc.w = fmaf(a, v.w, acc.w);
    }
    float4 bb = ((const float4*)b2)[tid];
    acc.x = fmaxf(acc.x + bb.x, 0.f);
    acc.y = fmaxf(acc.y + bb.y, 0.f);
    acc.z = fmaxf(acc.z + bb.z, 0.f);
    acc.w = fmaxf(acc.w + bb.w, 0.f);
    ((float4*)(out + (size_t)n * DD))[tid] = acc;
}

// ---------------- launcher ----------------
template <typename T>
static T* sym_p(const void* sym) {
    void* p = nullptr;
    cudaGetSymbolAddress(&p, sym);
    return (T*)p;
}

extern "C" void kernel_launch(void* const* d_in, const int* in_sizes, int n_in,
                              void* d_out, int out_size) {
    const float* x      = (const float*)d_in[0];
    const int*   adj    = (const int*)d_in[1];
    const float* W_fc   = (const float*)d_in[2];
    const float* b_fc   = (const float*)d_in[3];
    const float* W1     = (const float*)d_in[4];
    const float* a1_src = (const float*)d_in[5];
    const float* a1_dst = (const float*)d_in[6];
    const float* b1     = (const float*)d_in[7];
    const float* W2     = (const float*)d_in[8];
    const float* a2_src = (const float*)d_in[9];
    const float* a2_dst = (const float*)d_in[10];
    const float* b2     = (const float*)d_in[11];
    float* out = (float*)d_out;

    uint32_t* p_xp  = sym_p<uint32_t>(g_xp);
    uint32_t* p_h0p = sym_p<uint32_t>(g_h0p);
    uint32_t* p_h1p = sym_p<uint32_t>(g_h1p);
    float*    p_g1  = sym_p<float>(g_g1);
    float*    p_g2  = sym_p<float>(g_g2);
    uint4*    p_wfc = sym_p<uint4>(g_wfcp);
    uint4*    p_w1  = sym_p<uint4>(g_w1p);
    uint4*    p_w2  = sym_p<uint4>(g_w2p);

    const int dyn = NSTG * STG_BYTES;   // 64 KB
    cudaFuncSetAttribute(tgemm_p_kernel<0>,
                         cudaFuncAttributeMaxDynamicSharedMemorySize, dyn);
    cudaFuncSetAttribute(tgemm_p_kernel<1>,
                         cudaFuncAttributeMaxDynamicSharedMemorySize, dyn);

    // packs (launches 1-4), zero (5) — puts GEMM1 at launch slot 6 for ncu -s 5
    pack_a_kernel<<<(NN * H1C / 2 + 255) / 256, 256>>>(x, p_xp, NN * H1C / 2);
    pack_b_kernel<<<((H1C / 4) * H1C + 255) / 256, 256>>>(W_fc, p_wfc, H1C, H1C);
    pack_b_kernel<<<((H1C / 4) * DD + 255) / 256, 256>>>(W1, p_w1, H1C, DD);
    pack_b_kernel<<<((DD / 4) * DD + 255) / 256, 256>>>(W2, p_w2, DD, DD);
    zero_kernel<<<(NN + 255) / 256, 256>>>();

    // fc + relu -> packed h0   (launch 6 — profiled)
    {
        dim3 grid(H1C / 128, NN / 128);
        tgemm_p_kernel<1><<<grid, 256, dyn>>>(p_xp, p_wfc, b_fc, p_h0p, NN, H1C, H1C);
    }
    // g1 = h0 @ W1 (fp32)
    {
        dim3 grid(DD / 128, NN / 128);
        tgemm_p_kernel<0><<<grid, 256, dyn>>>(p_h0p, p_w1, nullptr, p_g1, NN, DD, H1C);
    }

    // CSR (needed before alpha/agg)
    count_kernel<<<(EE + 255) / 256, 256>>>(adj);
    scan_kernel<<<1, 256>>>();
    scatter_kernel<<<(EE + 255) / 256, 256>>>(adj);

    al1_kernel<<<(NN * 32 + 255) / 256, 256>>>(a1_src, a1_dst);
    alpha1_kernel<<<(NN * 32 + 255) / 256, 256>>>();
    agg1_kernel<<<NN, 128>>>(b1);          // -> packed h1

    // g2 = h1 @ W2 (fp32)
    {
        dim3 grid(DD / 128, NN / 128);
        tgemm_p_kernel<0><<<grid, 256, dyn>>>(p_h1p, p_w2, nullptr, p_g2, NN, DD, DD);
    }
    al2_kernel<<<(NN * 32 + 255) / 256, 256>>>(a2_src, a2_dst);
    alpha2_kernel<<<(NN * 32 + 255) / 256, 256>>>();
    agg2_kernel<<<NN, 128>>>(b2, out);
}